// round 2
// baseline (speedup 1.0000x reference)
#include <cuda_runtime.h>
#include <math.h>

// ---------------- problem constants ----------------
#define DIM     768
#define HEADS   12
#define DH      64
#define WIN     14
#define NW      196          // WIN*WIN
#define BATCH   8
#define H0      64
#define W0      64
#define NTOK    4096         // H0*W0
#define NWIN_D  5            // windows per spatial dim (70/14)
#define NWIN_B  25           // windows per batch image
#define NWINTOT 200          // BATCH * NWIN_B
#define MWIN    (NWINTOT*NW) // 39200 windowed tokens
#define MTOK    (BATCH*NTOK) // 32768 real tokens
#define MLP_H   3072
#define QKV_N   (3*DIM)      // 2304
#define SCALE   0.125f
#define EPS     1e-5f

// ---------------- scratch (static device globals; no allocations) ----------------
__device__ float g_xw[(size_t)MWIN * DIM];        // windowed LN1 output (zeros in pad)
__device__ float g_qkv[(size_t)MWIN * QKV_N];     // qkv projections
__device__ float g_attnout[(size_t)MWIN * DIM];   // attention output (pre-proj)
__device__ float g_x1[(size_t)MTOK * DIM];        // x + attn branch (residual 1)
__device__ float g_ln2[(size_t)MTOK * DIM];       // LN2 output
__device__ float g_mlp[(size_t)MTOK * MLP_H];     // GELU(fc1) output

// ---------------- block reduction ----------------
__device__ __forceinline__ float block_reduce_sum_256(float v) {
    __shared__ float red[8];
    int lane = threadIdx.x & 31, wid = threadIdx.x >> 5;
#pragma unroll
    for (int o = 16; o; o >>= 1) v += __shfl_xor_sync(0xffffffffu, v, o);
    __syncthreads();
    if (lane == 0) red[wid] = v;
    __syncthreads();
    float s = red[0];
#pragma unroll
    for (int i = 1; i < 8; i++) s += red[i];
    return s;
}

// ---------------- LN1 + window partition (pads -> zero rows) ----------------
__global__ void __launch_bounds__(256)
ln1_window_kernel(const float* __restrict__ x,
                  const float* __restrict__ g,
                  const float* __restrict__ b,
                  float* __restrict__ y) {
    int wt = blockIdx.x;                  // windowed-token index [0, MWIN)
    int wi = wt / NW, t = wt - wi * NW;
    int bb = wi / NWIN_B;
    int wrem = wi - bb * NWIN_B;
    int wr = wrem / NWIN_D, wc = wrem - wr * NWIN_D;
    int row = wr * WIN + t / WIN;
    int col = wc * WIN + (t % WIN);
    int tid = threadIdx.x;
    float* yr = y + (size_t)wt * DIM;
    if (row >= H0 || col >= W0) {
        yr[tid] = 0.f; yr[tid + 256] = 0.f; yr[tid + 512] = 0.f;
        return;
    }
    const float* xr = x + ((size_t)bb * NTOK + row * W0 + col) * DIM;
    float v0 = xr[tid], v1 = xr[tid + 256], v2 = xr[tid + 512];
    float mean = block_reduce_sum_256(v0 + v1 + v2) * (1.0f / DIM);
    float d0 = v0 - mean, d1 = v1 - mean, d2 = v2 - mean;
    float var = block_reduce_sum_256(d0 * d0 + d1 * d1 + d2 * d2) * (1.0f / DIM);
    float rs = rsqrtf(var + EPS);
    yr[tid]       = d0 * rs * g[tid]       + b[tid];
    yr[tid + 256] = d1 * rs * g[tid + 256] + b[tid + 256];
    yr[tid + 512] = d2 * rs * g[tid + 512] + b[tid + 512];
}

// ---------------- plain LN (rows of 768) ----------------
__global__ void __launch_bounds__(256)
ln_kernel(const float* __restrict__ in,
          const float* __restrict__ g,
          const float* __restrict__ b,
          float* __restrict__ out) {
    size_t row = blockIdx.x;
    int tid = threadIdx.x;
    const float* xr = in + row * DIM;
    float v0 = xr[tid], v1 = xr[tid + 256], v2 = xr[tid + 512];
    float mean = block_reduce_sum_256(v0 + v1 + v2) * (1.0f / DIM);
    float d0 = v0 - mean, d1 = v1 - mean, d2 = v2 - mean;
    float var = block_reduce_sum_256(d0 * d0 + d1 * d1 + d2 * d2) * (1.0f / DIM);
    float rs = rsqrtf(var + EPS);
    float* yr = out + row * DIM;
    yr[tid]       = d0 * rs * g[tid]       + b[tid];
    yr[tid + 256] = d1 * rs * g[tid + 256] + b[tid + 256];
    yr[tid + 512] = d2 * rs * g[tid + 512] + b[tid + 512];
}

// ---------------- generic NT GEMM: C[M,N] = A[M,K] * W[N,K]^T + bias ----------------
// EPI 0: store C
// EPI 1: window-revert scatter: x1[pos] = x[pos] + val (pad tokens dropped); C=g_x1, extra=x
// EPI 2: store gelu_exact(val)
// EPI 3: store val + extra[m*N+n]   (fc2 + residual, writes d_out)
template <int EPI>
__global__ void __launch_bounds__(256)
gemm_nt(const float* __restrict__ A, const float* __restrict__ W,
        const float* __restrict__ bias, float* __restrict__ C,
        const float* __restrict__ extra, int M, int N, int K) {
    __shared__ float sA[16][64];
    __shared__ float sB[16][64];
    const int tid = threadIdx.x;
    const int row0 = blockIdx.x * 64, col0 = blockIdx.y * 64;
    float acc[4][4] = {};
    for (int kt = 0; kt < K; kt += 16) {
#pragma unroll
        for (int it = 0; it < 4; it++) {
            int idx = tid + it * 256;
            int ml = idx >> 4, kl = idx & 15;
            int gm = row0 + ml;
            sA[kl][ml] = (gm < M) ? A[(size_t)gm * K + kt + kl] : 0.f;
            sB[kl][ml] = W[(size_t)(col0 + ml) * K + kt + kl];
        }
        __syncthreads();
#pragma unroll
        for (int k = 0; k < 16; k++) {
            float4 a = *(const float4*)&sA[k][(tid >> 4) * 4];
            float4 bv = *(const float4*)&sB[k][(tid & 15) * 4];
            acc[0][0] += a.x * bv.x; acc[0][1] += a.x * bv.y; acc[0][2] += a.x * bv.z; acc[0][3] += a.x * bv.w;
            acc[1][0] += a.y * bv.x; acc[1][1] += a.y * bv.y; acc[1][2] += a.y * bv.z; acc[1][3] += a.y * bv.w;
            acc[2][0] += a.z * bv.x; acc[2][1] += a.z * bv.y; acc[2][2] += a.z * bv.z; acc[2][3] += a.z * bv.w;
            acc[3][0] += a.w * bv.x; acc[3][1] += a.w * bv.y; acc[3][2] += a.w * bv.z; acc[3][3] += a.w * bv.w;
        }
        __syncthreads();
    }
    int tm0 = row0 + (tid >> 4) * 4;
    int tn0 = col0 + (tid & 15) * 4;
#pragma unroll
    for (int i = 0; i < 4; i++) {
        int m = tm0 + i;
        if (m >= M) continue;
        if (EPI == 1) {
            int wi = m / NW, t = m - wi * NW;
            int bb = wi / NWIN_B;
            int wrem = wi - bb * NWIN_B;
            int wr = wrem / NWIN_D, wc = wrem - wr * NWIN_D;
            int r = wr * WIN + t / WIN;
            int cc = wc * WIN + (t % WIN);
            if (r < H0 && cc < W0) {
                size_t o = ((size_t)bb * NTOK + r * W0 + cc) * DIM + tn0;
#pragma unroll
                for (int j = 0; j < 4; j++) {
                    float val = acc[i][j] + bias[tn0 + j];
                    C[o + j] = extra[o + j] + val;
                }
            }
        } else {
#pragma unroll
            for (int j = 0; j < 4; j++) {
                int n = tn0 + j;
                float val = acc[i][j] + bias[n];
                size_t o = (size_t)m * N + n;
                if (EPI == 0) {
                    C[o] = val;
                } else if (EPI == 2) {
                    C[o] = 0.5f * val * (1.0f + erff(val * 0.70710678118654752f));
                } else { // EPI == 3
                    C[o] = val + extra[o];
                }
            }
        }
    }
}

// ---------------- windowed attention, one (window, head) per block ----------------
// q in registers (scaled), K/V in dynamic smem, online softmax, acc[64] in regs.
__global__ void __launch_bounds__(224)
attn_kernel(const float* __restrict__ qkv,
            const float* __restrict__ rel,
            float* __restrict__ outp) {
    extern __shared__ float sm[];
    float* sk = sm;             // NW*DH = 12544 floats
    float* sv = sm + NW * DH;   // 12544 floats
    int wi = blockIdx.x / HEADS;
    int h  = blockIdx.x - wi * HEADS;
    int tid = threadIdx.x;
    size_t base = (size_t)wi * NW * QKV_N + h * DH;
    for (int idx = tid; idx < NW * DH; idx += 224) {
        int t = idx >> 6, d = idx & 63;
        size_t o = base + (size_t)t * QKV_N + d;
        sk[idx] = qkv[o + DIM];
        sv[idx] = qkv[o + 2 * DIM];
    }
    __syncthreads();
    if (tid >= NW) return;

    float q[DH];
    {
        const float4* qp = (const float4*)(qkv + base + (size_t)tid * QKV_N);
#pragma unroll
        for (int i = 0; i < 16; i++) {
            float4 qq = qp[i];
            q[4 * i]     = qq.x * SCALE;
            q[4 * i + 1] = qq.y * SCALE;
            q[4 * i + 2] = qq.z * SCALE;
            q[4 * i + 3] = qq.w * SCALE;
        }
    }
    float acc[DH];
#pragma unroll
    for (int i = 0; i < DH; i++) acc[i] = 0.f;
    float mx = -1e30f, l = 0.f;
    const float* brow = rel + ((size_t)h * NW + tid) * NW;

    for (int j = 0; j < NW; j++) {
        const float4* kp = (const float4*)(sk + j * DH);
        float s = 0.f;
#pragma unroll
        for (int i = 0; i < 16; i++) {
            float4 kk = kp[i];
            s += q[4 * i] * kk.x + q[4 * i + 1] * kk.y
               + q[4 * i + 2] * kk.z + q[4 * i + 3] * kk.w;
        }
        s += brow[j];
        const float4* vp = (const float4*)(sv + j * DH);
        if (s <= mx) {
            float p = __expf(s - mx);
            l += p;
#pragma unroll
            for (int i = 0; i < 16; i++) {
                float4 vv = vp[i];
                acc[4 * i]     += p * vv.x;
                acc[4 * i + 1] += p * vv.y;
                acc[4 * i + 2] += p * vv.z;
                acc[4 * i + 3] += p * vv.w;
            }
        } else {
            float c = __expf(mx - s);
            l = l * c + 1.f;
            mx = s;
#pragma unroll
            for (int i = 0; i < 16; i++) {
                float4 vv = vp[i];
                acc[4 * i]     = acc[4 * i]     * c + vv.x;
                acc[4 * i + 1] = acc[4 * i + 1] * c + vv.y;
                acc[4 * i + 2] = acc[4 * i + 2] * c + vv.z;
                acc[4 * i + 3] = acc[4 * i + 3] * c + vv.w;
            }
        }
    }
    float inv = 1.0f / l;
    float4* op = (float4*)(outp + (size_t)(wi * NW + tid) * DIM + h * DH);
#pragma unroll
    for (int i = 0; i < 16; i++) {
        op[i] = make_float4(acc[4 * i] * inv, acc[4 * i + 1] * inv,
                            acc[4 * i + 2] * inv, acc[4 * i + 3] * inv);
    }
}

// ---------------- launcher ----------------
extern "C" void kernel_launch(void* const* d_in, const int* in_sizes, int n_in,
                              void* d_out, int out_size) {
    const float* x      = (const float*)d_in[0];
    const float* rel    = (const float*)d_in[1];
    const float* ln1_g  = (const float*)d_in[2];
    const float* ln1_b  = (const float*)d_in[3];
    const float* qkv_w  = (const float*)d_in[4];
    const float* qkv_b  = (const float*)d_in[5];
    const float* proj_w = (const float*)d_in[6];
    const float* proj_b = (const float*)d_in[7];
    const float* ln2_g  = (const float*)d_in[8];
    const float* ln2_b  = (const float*)d_in[9];
    const float* fc1_w  = (const float*)d_in[10];
    const float* fc1_b  = (const float*)d_in[11];
    const float* fc2_w  = (const float*)d_in[12];
    const float* fc2_b  = (const float*)d_in[13];
    float* out = (float*)d_out;

    float *p_xw, *p_qkv, *p_attnout, *p_x1, *p_ln2, *p_mlp;
    cudaGetSymbolAddress((void**)&p_xw,      g_xw);
    cudaGetSymbolAddress((void**)&p_qkv,     g_qkv);
    cudaGetSymbolAddress((void**)&p_attnout, g_attnout);
    cudaGetSymbolAddress((void**)&p_x1,      g_x1);
    cudaGetSymbolAddress((void**)&p_ln2,     g_ln2);
    cudaGetSymbolAddress((void**)&p_mlp,     g_mlp);

    const int attn_smem = 2 * NW * DH * (int)sizeof(float);  // 100352 B
    cudaFuncSetAttribute(attn_kernel, cudaFuncAttributeMaxDynamicSharedMemorySize, attn_smem);

    // 1. LN1 + window partition (zeros in padded tokens)
    ln1_window_kernel<<<MWIN, 256>>>(x, ln1_g, ln1_b, p_xw);

    // 2. QKV: [39200, 2304] = xw @ qkv_w^T + b
    gemm_nt<0><<<dim3((MWIN + 63) / 64, QKV_N / 64), 256>>>(
        p_xw, qkv_w, qkv_b, p_qkv, nullptr, MWIN, QKV_N, DIM);

    // 3. Windowed attention with relative position bias
    attn_kernel<<<NWINTOT * HEADS, 224, attn_smem>>>(p_qkv, rel, p_attnout);

    // 4. Projection + window revert + residual -> g_x1
    gemm_nt<1><<<dim3((MWIN + 63) / 64, DIM / 64), 256>>>(
        p_attnout, proj_w, proj_b, p_x1, x, MWIN, DIM, DIM);

    // 5. LN2
    ln_kernel<<<MTOK, 256>>>(p_x1, ln2_g, ln2_b, p_ln2);

    // 6. fc1 + exact GELU
    gemm_nt<2><<<dim3(MTOK / 64, MLP_H / 64), 256>>>(
        p_ln2, fc1_w, fc1_b, p_mlp, nullptr, MTOK, MLP_H, DIM);

    // 7. fc2 + residual -> d_out
    gemm_nt<3><<<dim3(MTOK / 64, DIM / 64), 256>>>(
        p_mlp, fc2_w, fc2_b, out, p_x1, MTOK, DIM, MLP_H);
}

// round 3
// speedup vs baseline: 1.2177x; 1.2177x over previous
#include <cuda_runtime.h>
#include <math.h>

// ---------------- problem constants ----------------
#define DIM     768
#define HEADS   12
#define DH      64
#define WIN     14
#define NW      196          // WIN*WIN
#define BATCH   8
#define H0      64
#define W0      64
#define NTOK    4096         // H0*W0
#define NWIN_D  5            // windows per spatial dim (70/14)
#define NWIN_B  25           // windows per batch image
#define NWINTOT 200          // BATCH * NWIN_B
#define MWIN    (NWINTOT*NW) // 39200 windowed tokens
#define MTOK    (BATCH*NTOK) // 32768 real tokens
#define MLP_H   3072
#define QKV_N   (3*DIM)      // 2304
#define SCALE   0.125f
#define EPS     1e-5f

// ---------------- scratch (static device globals; no allocations) ----------------
__device__ float g_xw[(size_t)MWIN * DIM];        // windowed LN1 output (zeros in pad)
__device__ float g_qkv[(size_t)MWIN * QKV_N];     // qkv projections
__device__ float g_attnout[(size_t)MWIN * DIM];   // attention output (pre-proj)
__device__ float g_x1[(size_t)MTOK * DIM];        // x + attn branch (residual 1)
__device__ float g_ln2[(size_t)MTOK * DIM];       // LN2 output
__device__ float g_mlp[(size_t)MTOK * MLP_H];     // GELU(fc1) output

// ---------------- block reduction ----------------
__device__ __forceinline__ float block_reduce_sum_256(float v) {
    __shared__ float red[8];
    int lane = threadIdx.x & 31, wid = threadIdx.x >> 5;
#pragma unroll
    for (int o = 16; o; o >>= 1) v += __shfl_xor_sync(0xffffffffu, v, o);
    __syncthreads();
    if (lane == 0) red[wid] = v;
    __syncthreads();
    float s = red[0];
#pragma unroll
    for (int i = 1; i < 8; i++) s += red[i];
    return s;
}

// ---------------- LN1 + window partition (pads -> zero rows) ----------------
__global__ void __launch_bounds__(256)
ln1_window_kernel(const float* __restrict__ x,
                  const float* __restrict__ g,
                  const float* __restrict__ b,
                  float* __restrict__ y) {
    int wt = blockIdx.x;                  // windowed-token index [0, MWIN)
    int wi = wt / NW, t = wt - wi * NW;
    int bb = wi / NWIN_B;
    int wrem = wi - bb * NWIN_B;
    int wr = wrem / NWIN_D, wc = wrem - wr * NWIN_D;
    int row = wr * WIN + t / WIN;
    int col = wc * WIN + (t % WIN);
    int tid = threadIdx.x;
    float* yr = y + (size_t)wt * DIM;
    if (row >= H0 || col >= W0) {
        yr[tid] = 0.f; yr[tid + 256] = 0.f; yr[tid + 512] = 0.f;
        return;
    }
    const float* xr = x + ((size_t)bb * NTOK + row * W0 + col) * DIM;
    float v0 = xr[tid], v1 = xr[tid + 256], v2 = xr[tid + 512];
    float mean = block_reduce_sum_256(v0 + v1 + v2) * (1.0f / DIM);
    float d0 = v0 - mean, d1 = v1 - mean, d2 = v2 - mean;
    float var = block_reduce_sum_256(d0 * d0 + d1 * d1 + d2 * d2) * (1.0f / DIM);
    float rs = rsqrtf(var + EPS);
    yr[tid]       = d0 * rs * g[tid]       + b[tid];
    yr[tid + 256] = d1 * rs * g[tid + 256] + b[tid + 256];
    yr[tid + 512] = d2 * rs * g[tid + 512] + b[tid + 512];
}

// ---------------- plain LN (rows of 768) ----------------
__global__ void __launch_bounds__(256)
ln_kernel(const float* __restrict__ in,
          const float* __restrict__ g,
          const float* __restrict__ b,
          float* __restrict__ out) {
    size_t row = blockIdx.x;
    int tid = threadIdx.x;
    const float* xr = in + row * DIM;
    float v0 = xr[tid], v1 = xr[tid + 256], v2 = xr[tid + 512];
    float mean = block_reduce_sum_256(v0 + v1 + v2) * (1.0f / DIM);
    float d0 = v0 - mean, d1 = v1 - mean, d2 = v2 - mean;
    float var = block_reduce_sum_256(d0 * d0 + d1 * d1 + d2 * d2) * (1.0f / DIM);
    float rs = rsqrtf(var + EPS);
    float* yr = out + row * DIM;
    yr[tid]       = d0 * rs * g[tid]       + b[tid];
    yr[tid + 256] = d1 * rs * g[tid + 256] + b[tid + 256];
    yr[tid + 512] = d2 * rs * g[tid + 512] + b[tid + 512];
}

// ---------------- 128x128x8 double-buffered SGEMM (NT) ----------------
// C[M,N] = A[M,K] * W[N,K]^T + bias, with fused epilogues:
//  EPI 0: store C
//  EPI 1: window-revert scatter: C[pos] = extra[pos] + val (pad tokens dropped)
//  EPI 2: store exact GELU(val)
//  EPI 3: store val + extra[m*N+n]
template <int EPI>
__global__ void __launch_bounds__(256)
sgemm128(const float* __restrict__ A, const float* __restrict__ W,
         const float* __restrict__ bias, float* __restrict__ C,
         const float* __restrict__ extra, int M, int N, int K) {
    __shared__ float sA[2][8][132];
    __shared__ float sB[2][8][132];
    const int tid  = threadIdx.x;
    const int row0 = blockIdx.x * 128, col0 = blockIdx.y * 128;

    // gmem load mapping: thread -> (row = tid>>1, k-quad = (tid&1)*4)
    const int lr = tid >> 1;
    const int lk = (tid & 1) * 4;
    const bool aval = (row0 + lr) < M;
    const float* Ap = A + (size_t)(row0 + lr) * K + lk;
    const float* Bp = W + (size_t)(col0 + lr) * K + lk;

    const int tx = tid & 15, ty = tid >> 4;  // 16x16 thread grid, 8x8 microtile
    float acc[8][8] = {};

    const int nt = K >> 3;
    float4 ra = aval ? *(const float4*)Ap : make_float4(0.f, 0.f, 0.f, 0.f);
    float4 rb = *(const float4*)Bp;
    sA[0][lk + 0][lr] = ra.x; sA[0][lk + 1][lr] = ra.y;
    sA[0][lk + 2][lr] = ra.z; sA[0][lk + 3][lr] = ra.w;
    sB[0][lk + 0][lr] = rb.x; sB[0][lk + 1][lr] = rb.y;
    sB[0][lk + 2][lr] = rb.z; sB[0][lk + 3][lr] = rb.w;
    __syncthreads();

    for (int kt = 0; kt < nt; kt++) {
        const int cur = kt & 1;
        if (kt + 1 < nt) {
            const float* ap = Ap + (size_t)(kt + 1) * 8;
            const float* bp = Bp + (size_t)(kt + 1) * 8;
            ra = aval ? *(const float4*)ap : make_float4(0.f, 0.f, 0.f, 0.f);
            rb = *(const float4*)bp;
        }
#pragma unroll
        for (int k = 0; k < 8; k++) {
            float a[8], b[8];
            *(float4*)(a)     = *(const float4*)&sA[cur][k][ty * 8];
            *(float4*)(a + 4) = *(const float4*)&sA[cur][k][ty * 8 + 4];
            *(float4*)(b)     = *(const float4*)&sB[cur][k][tx * 8];
            *(float4*)(b + 4) = *(const float4*)&sB[cur][k][tx * 8 + 4];
#pragma unroll
            for (int i = 0; i < 8; i++)
#pragma unroll
                for (int j = 0; j < 8; j++)
                    acc[i][j] += a[i] * b[j];
        }
        if (kt + 1 < nt) {
            const int nxt = cur ^ 1;
            sA[nxt][lk + 0][lr] = ra.x; sA[nxt][lk + 1][lr] = ra.y;
            sA[nxt][lk + 2][lr] = ra.z; sA[nxt][lk + 3][lr] = ra.w;
            sB[nxt][lk + 0][lr] = rb.x; sB[nxt][lk + 1][lr] = rb.y;
            sB[nxt][lk + 2][lr] = rb.z; sB[nxt][lk + 3][lr] = rb.w;
            __syncthreads();
        }
    }

    // epilogue
    float bcol[8];
#pragma unroll
    for (int j = 0; j < 8; j++) bcol[j] = bias[col0 + tx * 8 + j];

#pragma unroll
    for (int i = 0; i < 8; i++) {
        int m = row0 + ty * 8 + i;
        if (m >= M) continue;
        int tn0 = col0 + tx * 8;
        if (EPI == 1) {
            int wi = m / NW, t = m - wi * NW;
            int bb = wi / NWIN_B;
            int wrem = wi - bb * NWIN_B;
            int wr = wrem / NWIN_D, wc = wrem - wr * NWIN_D;
            int r  = wr * WIN + t / WIN;
            int cc = wc * WIN + (t % WIN);
            if (r < H0 && cc < W0) {
                size_t o = ((size_t)bb * NTOK + r * W0 + cc) * DIM + tn0;
#pragma unroll
                for (int j = 0; j < 8; j++)
                    C[o + j] = extra[o + j] + acc[i][j] + bcol[j];
            }
        } else {
            size_t o = (size_t)m * N + tn0;
            if (EPI == 0) {
                float4 v0 = make_float4(acc[i][0] + bcol[0], acc[i][1] + bcol[1],
                                        acc[i][2] + bcol[2], acc[i][3] + bcol[3]);
                float4 v1 = make_float4(acc[i][4] + bcol[4], acc[i][5] + bcol[5],
                                        acc[i][6] + bcol[6], acc[i][7] + bcol[7]);
                *(float4*)&C[o]     = v0;
                *(float4*)&C[o + 4] = v1;
            } else if (EPI == 2) {
#pragma unroll
                for (int j = 0; j < 8; j++) {
                    float val = acc[i][j] + bcol[j];
                    C[o + j] = 0.5f * val * (1.0f + erff(val * 0.70710678118654752f));
                }
            } else { // EPI == 3
#pragma unroll
                for (int j = 0; j < 8; j++)
                    C[o + j] = acc[i][j] + bcol[j] + extra[o + j];
            }
        }
    }
}

// ---------------- windowed attention, one (window, head) per block ----------------
__global__ void __launch_bounds__(224)
attn_kernel(const float* __restrict__ qkv,
            const float* __restrict__ rel,
            float* __restrict__ outp) {
    extern __shared__ float sm[];
    float* sk = sm;             // NW*DH floats
    float* sv = sm + NW * DH;
    int wi = blockIdx.x / HEADS;
    int h  = blockIdx.x - wi * HEADS;
    int tid = threadIdx.x;
    size_t base = (size_t)wi * NW * QKV_N + h * DH;
    for (int idx = tid; idx < NW * DH; idx += 224) {
        int t = idx >> 6, d = idx & 63;
        size_t o = base + (size_t)t * QKV_N + d;
        sk[idx] = qkv[o + DIM];
        sv[idx] = qkv[o + 2 * DIM];
    }
    __syncthreads();
    if (tid >= NW) return;

    float q[DH];
    {
        const float4* qp = (const float4*)(qkv + base + (size_t)tid * QKV_N);
#pragma unroll
        for (int i = 0; i < 16; i++) {
            float4 qq = qp[i];
            q[4 * i]     = qq.x * SCALE;
            q[4 * i + 1] = qq.y * SCALE;
            q[4 * i + 2] = qq.z * SCALE;
            q[4 * i + 3] = qq.w * SCALE;
        }
    }
    float acc[DH];
#pragma unroll
    for (int i = 0; i < DH; i++) acc[i] = 0.f;
    float mx = -1e30f, l = 0.f;
    const float* brow = rel + ((size_t)h * NW + tid) * NW;

    for (int j = 0; j < NW; j++) {
        const float4* kp = (const float4*)(sk + j * DH);
        float s = 0.f;
#pragma unroll
        for (int i = 0; i < 16; i++) {
            float4 kk = kp[i];
            s += q[4 * i] * kk.x + q[4 * i + 1] * kk.y
               + q[4 * i + 2] * kk.z + q[4 * i + 3] * kk.w;
        }
        s += brow[j];
        const float4* vp = (const float4*)(sv + j * DH);
        if (s <= mx) {
            float p = __expf(s - mx);
            l += p;
#pragma unroll
            for (int i = 0; i < 16; i++) {
                float4 vv = vp[i];
                acc[4 * i]     += p * vv.x;
                acc[4 * i + 1] += p * vv.y;
                acc[4 * i + 2] += p * vv.z;
                acc[4 * i + 3] += p * vv.w;
            }
        } else {
            float c = __expf(mx - s);
            l = l * c + 1.f;
            mx = s;
#pragma unroll
            for (int i = 0; i < 16; i++) {
                float4 vv = vp[i];
                acc[4 * i]     = acc[4 * i]     * c + vv.x;
                acc[4 * i + 1] = acc[4 * i + 1] * c + vv.y;
                acc[4 * i + 2] = acc[4 * i + 2] * c + vv.z;
                acc[4 * i + 3] = acc[4 * i + 3] * c + vv.w;
            }
        }
    }
    float inv = 1.0f / l;
    float4* op = (float4*)(outp + (size_t)(wi * NW + tid) * DIM + h * DH);
#pragma unroll
    for (int i = 0; i < 16; i++) {
        op[i] = make_float4(acc[4 * i] * inv, acc[4 * i + 1] * inv,
                            acc[4 * i + 2] * inv, acc[4 * i + 3] * inv);
    }
}

// ---------------- launcher ----------------
extern "C" void kernel_launch(void* const* d_in, const int* in_sizes, int n_in,
                              void* d_out, int out_size) {
    const float* x      = (const float*)d_in[0];
    const float* rel    = (const float*)d_in[1];
    const float* ln1_g  = (const float*)d_in[2];
    const float* ln1_b  = (const float*)d_in[3];
    const float* qkv_w  = (const float*)d_in[4];
    const float* qkv_b  = (const float*)d_in[5];
    const float* proj_w = (const float*)d_in[6];
    const float* proj_b = (const float*)d_in[7];
    const float* ln2_g  = (const float*)d_in[8];
    const float* ln2_b  = (const float*)d_in[9];
    const float* fc1_w  = (const float*)d_in[10];
    const float* fc1_b  = (const float*)d_in[11];
    const float* fc2_w  = (const float*)d_in[12];
    const float* fc2_b  = (const float*)d_in[13];
    float* out = (float*)d_out;

    float *p_xw, *p_qkv, *p_attnout, *p_x1, *p_ln2, *p_mlp;
    cudaGetSymbolAddress((void**)&p_xw,      g_xw);
    cudaGetSymbolAddress((void**)&p_qkv,     g_qkv);
    cudaGetSymbolAddress((void**)&p_attnout, g_attnout);
    cudaGetSymbolAddress((void**)&p_x1,      g_x1);
    cudaGetSymbolAddress((void**)&p_ln2,     g_ln2);
    cudaGetSymbolAddress((void**)&p_mlp,     g_mlp);

    const int attn_smem = 2 * NW * DH * (int)sizeof(float);  // 100352 B
    cudaFuncSetAttribute(attn_kernel, cudaFuncAttributeMaxDynamicSharedMemorySize, attn_smem);

    // 1. LN1 + window partition (zeros in padded tokens)
    ln1_window_kernel<<<MWIN, 256>>>(x, ln1_g, ln1_b, p_xw);

    // 2. QKV: [39200, 2304] = xw @ qkv_w^T + b
    sgemm128<0><<<dim3((MWIN + 127) / 128, QKV_N / 128), 256>>>(
        p_xw, qkv_w, qkv_b, p_qkv, nullptr, MWIN, QKV_N, DIM);

    // 3. Windowed attention with relative position bias
    attn_kernel<<<NWINTOT * HEADS, 224, attn_smem>>>(p_qkv, rel, p_attnout);

    // 4. Projection + window revert + residual -> g_x1
    sgemm128<1><<<dim3((MWIN + 127) / 128, DIM / 128), 256>>>(
        p_attnout, proj_w, proj_b, p_x1, x, MWIN, DIM, DIM);

    // 5. LN2
    ln_kernel<<<MTOK, 256>>>(p_x1, ln2_g, ln2_b, p_ln2);

    // 6. fc1 + exact GELU
    sgemm128<2><<<dim3(MTOK / 128, MLP_H / 128), 256>>>(
        p_ln2, fc1_w, fc1_b, p_mlp, nullptr, MTOK, MLP_H, DIM);

    // 7. fc2 + residual -> d_out
    sgemm128<3><<<dim3(MTOK / 128, DIM / 128), 256>>>(
        p_mlp, fc2_w, fc2_b, out, p_x1, MTOK, DIM, MLP_H);
}

// round 4
// speedup vs baseline: 1.9620x; 1.6112x over previous
#include <cuda_runtime.h>
#include <math.h>

// ---------------- problem constants ----------------
#define DIM     768
#define HEADS   12
#define DH      64
#define WIN     14
#define NW      196          // WIN*WIN
#define BATCH   8
#define H0      64
#define W0      64
#define NTOK    4096         // H0*W0
#define NWIN_D  5            // windows per spatial dim (70/14)
#define NWIN_B  25           // windows per batch image
#define NWINTOT 200          // BATCH * NWIN_B
#define MWIN    (NWINTOT*NW) // 39200 windowed tokens
#define MTOK    (BATCH*NTOK) // 32768 real tokens
#define MLP_H   3072
#define QKV_N   (3*DIM)      // 2304
#define SCALE   0.125f
#define EPS     1e-5f

// ---------------- scratch (static device globals; no allocations) ----------------
__device__ float g_xw[(size_t)MWIN * DIM];        // windowed LN1 output (zeros in pad)
__device__ float g_qkv[(size_t)MWIN * QKV_N];     // qkv projections
__device__ float g_attnout[(size_t)MWIN * DIM];   // attention output (pre-proj)
__device__ float g_x1[(size_t)MTOK * DIM];        // x + attn branch (residual 1)
__device__ float g_ln2[(size_t)MTOK * DIM];       // LN2 output
__device__ float g_mlp[(size_t)MTOK * MLP_H];     // GELU(fc1) output

// ---------------- block reduction ----------------
__device__ __forceinline__ float block_reduce_sum_256(float v) {
    __shared__ float red[8];
    int lane = threadIdx.x & 31, wid = threadIdx.x >> 5;
#pragma unroll
    for (int o = 16; o; o >>= 1) v += __shfl_xor_sync(0xffffffffu, v, o);
    __syncthreads();
    if (lane == 0) red[wid] = v;
    __syncthreads();
    float s = red[0];
#pragma unroll
    for (int i = 1; i < 8; i++) s += red[i];
    return s;
}

// ---------------- LN1 + window partition (pads -> zero rows) ----------------
__global__ void __launch_bounds__(256)
ln1_window_kernel(const float* __restrict__ x,
                  const float* __restrict__ g,
                  const float* __restrict__ b,
                  float* __restrict__ y) {
    int wt = blockIdx.x;                  // windowed-token index [0, MWIN)
    int wi = wt / NW, t = wt - wi * NW;
    int bb = wi / NWIN_B;
    int wrem = wi - bb * NWIN_B;
    int wr = wrem / NWIN_D, wc = wrem - wr * NWIN_D;
    int row = wr * WIN + t / WIN;
    int col = wc * WIN + (t % WIN);
    int tid = threadIdx.x;
    float* yr = y + (size_t)wt * DIM;
    if (row >= H0 || col >= W0) {
        yr[tid] = 0.f; yr[tid + 256] = 0.f; yr[tid + 512] = 0.f;
        return;
    }
    const float* xr = x + ((size_t)bb * NTOK + row * W0 + col) * DIM;
    float v0 = xr[tid], v1 = xr[tid + 256], v2 = xr[tid + 512];
    float mean = block_reduce_sum_256(v0 + v1 + v2) * (1.0f / DIM);
    float d0 = v0 - mean, d1 = v1 - mean, d2 = v2 - mean;
    float var = block_reduce_sum_256(d0 * d0 + d1 * d1 + d2 * d2) * (1.0f / DIM);
    float rs = rsqrtf(var + EPS);
    yr[tid]       = d0 * rs * g[tid]       + b[tid];
    yr[tid + 256] = d1 * rs * g[tid + 256] + b[tid + 256];
    yr[tid + 512] = d2 * rs * g[tid + 512] + b[tid + 512];
}

// ---------------- plain LN (rows of 768) ----------------
__global__ void __launch_bounds__(256)
ln_kernel(const float* __restrict__ in,
          const float* __restrict__ g,
          const float* __restrict__ b,
          float* __restrict__ out) {
    size_t row = blockIdx.x;
    int tid = threadIdx.x;
    const float* xr = in + row * DIM;
    float v0 = xr[tid], v1 = xr[tid + 256], v2 = xr[tid + 512];
    float mean = block_reduce_sum_256(v0 + v1 + v2) * (1.0f / DIM);
    float d0 = v0 - mean, d1 = v1 - mean, d2 = v2 - mean;
    float var = block_reduce_sum_256(d0 * d0 + d1 * d1 + d2 * d2) * (1.0f / DIM);
    float rs = rsqrtf(var + EPS);
    float* yr = out + row * DIM;
    yr[tid]       = d0 * rs * g[tid]       + b[tid];
    yr[tid + 256] = d1 * rs * g[tid + 256] + b[tid + 256];
    yr[tid + 512] = d2 * rs * g[tid + 512] + b[tid + 512];
}

// ---------------- 128x128x8 double-buffered SGEMM (NT) ----------------
// C[M,N] = A[M,K] * W[N,K]^T + bias, with fused epilogues:
//  EPI 0: store C
//  EPI 1: window-revert scatter: C[pos] = extra[pos] + val (pad tokens dropped)
//  EPI 2: store exact GELU(val)
//  EPI 3: store val + extra[m*N+n]
template <int EPI>
__global__ void __launch_bounds__(256)
sgemm128(const float* __restrict__ A, const float* __restrict__ W,
         const float* __restrict__ bias, float* __restrict__ C,
         const float* __restrict__ extra, int M, int N, int K) {
    __shared__ float sA[2][8][132];
    __shared__ float sB[2][8][132];
    const int tid  = threadIdx.x;
    const int row0 = blockIdx.x * 128, col0 = blockIdx.y * 128;

    // gmem load mapping: thread -> (row = tid>>1, k-quad = (tid&1)*4)
    const int lr = tid >> 1;
    const int lk = (tid & 1) * 4;
    const bool aval = (row0 + lr) < M;
    const float* Ap = A + (size_t)(row0 + lr) * K + lk;
    const float* Bp = W + (size_t)(col0 + lr) * K + lk;

    const int tx = tid & 15, ty = tid >> 4;  // 16x16 thread grid, 8x8 microtile
    float acc[8][8] = {};

    const int nt = K >> 3;
    float4 ra = aval ? *(const float4*)Ap : make_float4(0.f, 0.f, 0.f, 0.f);
    float4 rb = *(const float4*)Bp;
    sA[0][lk + 0][lr] = ra.x; sA[0][lk + 1][lr] = ra.y;
    sA[0][lk + 2][lr] = ra.z; sA[0][lk + 3][lr] = ra.w;
    sB[0][lk + 0][lr] = rb.x; sB[0][lk + 1][lr] = rb.y;
    sB[0][lk + 2][lr] = rb.z; sB[0][lk + 3][lr] = rb.w;
    __syncthreads();

    for (int kt = 0; kt < nt; kt++) {
        const int cur = kt & 1;
        if (kt + 1 < nt) {
            const float* ap = Ap + (size_t)(kt + 1) * 8;
            const float* bp = Bp + (size_t)(kt + 1) * 8;
            ra = aval ? *(const float4*)ap : make_float4(0.f, 0.f, 0.f, 0.f);
            rb = *(const float4*)bp;
        }
#pragma unroll
        for (int k = 0; k < 8; k++) {
            float a[8], b[8];
            *(float4*)(a)     = *(const float4*)&sA[cur][k][ty * 8];
            *(float4*)(a + 4) = *(const float4*)&sA[cur][k][ty * 8 + 4];
            *(float4*)(b)     = *(const float4*)&sB[cur][k][tx * 8];
            *(float4*)(b + 4) = *(const float4*)&sB[cur][k][tx * 8 + 4];
#pragma unroll
            for (int i = 0; i < 8; i++)
#pragma unroll
                for (int j = 0; j < 8; j++)
                    acc[i][j] += a[i] * b[j];
        }
        if (kt + 1 < nt) {
            const int nxt = cur ^ 1;
            sA[nxt][lk + 0][lr] = ra.x; sA[nxt][lk + 1][lr] = ra.y;
            sA[nxt][lk + 2][lr] = ra.z; sA[nxt][lk + 3][lr] = ra.w;
            sB[nxt][lk + 0][lr] = rb.x; sB[nxt][lk + 1][lr] = rb.y;
            sB[nxt][lk + 2][lr] = rb.z; sB[nxt][lk + 3][lr] = rb.w;
            __syncthreads();
        }
    }

    // epilogue
    float bcol[8];
#pragma unroll
    for (int j = 0; j < 8; j++) bcol[j] = bias[col0 + tx * 8 + j];

#pragma unroll
    for (int i = 0; i < 8; i++) {
        int m = row0 + ty * 8 + i;
        if (m >= M) continue;
        int tn0 = col0 + tx * 8;
        if (EPI == 1) {
            int wi = m / NW, t = m - wi * NW;
            int bb = wi / NWIN_B;
            int wrem = wi - bb * NWIN_B;
            int wr = wrem / NWIN_D, wc = wrem - wr * NWIN_D;
            int r  = wr * WIN + t / WIN;
            int cc = wc * WIN + (t % WIN);
            if (r < H0 && cc < W0) {
                size_t o = ((size_t)bb * NTOK + r * W0 + cc) * DIM + tn0;
#pragma unroll
                for (int j = 0; j < 8; j++)
                    C[o + j] = extra[o + j] + acc[i][j] + bcol[j];
            }
        } else {
            size_t o = (size_t)m * N + tn0;
            if (EPI == 0) {
                float4 v0 = make_float4(acc[i][0] + bcol[0], acc[i][1] + bcol[1],
                                        acc[i][2] + bcol[2], acc[i][3] + bcol[3]);
                float4 v1 = make_float4(acc[i][4] + bcol[4], acc[i][5] + bcol[5],
                                        acc[i][6] + bcol[6], acc[i][7] + bcol[7]);
                *(float4*)&C[o]     = v0;
                *(float4*)&C[o + 4] = v1;
            } else if (EPI == 2) {
#pragma unroll
                for (int j = 0; j < 8; j++) {
                    float val = acc[i][j] + bcol[j];
                    C[o + j] = 0.5f * val * (1.0f + erff(val * 0.70710678118654752f));
                }
            } else { // EPI == 3
#pragma unroll
                for (int j = 0; j < 8; j++)
                    C[o + j] = acc[i][j] + bcol[j] + extra[o + j];
            }
        }
    }
}

// ---------------- windowed attention, one (window, head) per block ----------------
__global__ void __launch_bounds__(224)
attn_kernel(const float* __restrict__ qkv,
            const float* __restrict__ rel,
            float* __restrict__ outp) {
    extern __shared__ float sm[];
    float* sk = sm;             // NW*DH floats
    float* sv = sm + NW * DH;
    int wi = blockIdx.x / HEADS;
    int h  = blockIdx.x - wi * HEADS;
    int tid = threadIdx.x;
    size_t base = (size_t)wi * NW * QKV_N + h * DH;
    for (int idx = tid; idx < NW * DH; idx += 224) {
        int t = idx >> 6, d = idx & 63;
        size_t o = base + (size_t)t * QKV_N + d;
        sk[idx] = qkv[o + DIM];
        sv[idx] = qkv[o + 2 * DIM];
    }
    __syncthreads();
    if (tid >= NW) return;

    float q[DH];
    {
        const float4* qp = (const float4*)(qkv + base + (size_t)tid * QKV_N);
#pragma unroll
        for (int i = 0; i < 16; i++) {
            float4 qq = qp[i];
            q[4 * i]     = qq.x * SCALE;
            q[4 * i + 1] = qq.y * SCALE;
            q[4 * i + 2] = qq.z * SCALE;
            q[4 * i + 3] = qq.w * SCALE;
        }
    }
    float acc[DH];
#pragma unroll
    for (int i = 0; i < DH; i++) acc[i] = 0.f;
    float mx = -1e30f, l = 0.f;
    const float* brow = rel + ((size_t)h * NW + tid) * NW;

    for (int j = 0; j < NW; j++) {
        const float4* kp = (const float4*)(sk + j * DH);
        float s = 0.f;
#pragma unroll
        for (int i = 0; i < 16; i++) {
            float4 kk = kp[i];
            s += q[4 * i] * kk.x + q[4 * i + 1] * kk.y
               + q[4 * i + 2] * kk.z + q[4 * i + 3] * kk.w;
        }
        s += brow[j];
        const float4* vp = (const float4*)(sv + j * DH);
        if (s <= mx) {
            float p = __expf(s - mx);
            l += p;
#pragma unroll
            for (int i = 0; i < 16; i++) {
                float4 vv = vp[i];
                acc[4 * i]     += p * vv.x;
                acc[4 * i + 1] += p * vv.y;
                acc[4 * i + 2] += p * vv.z;
                acc[4 * i + 3] += p * vv.w;
            }
        } else {
            float c = __expf(mx - s);
            l = l * c + 1.f;
            mx = s;
#pragma unroll
            for (int i = 0; i < 16; i++) {
                float4 vv = vp[i];
                acc[4 * i]     = acc[4 * i]     * c + vv.x;
                acc[4 * i + 1] = acc[4 * i + 1] * c + vv.y;
                acc[4 * i + 2] = acc[4 * i + 2] * c + vv.z;
                acc[4 * i + 3] = acc[4 * i + 3] * c + vv.w;
            }
        }
    }
    float inv = 1.0f / l;
    float4* op = (float4*)(outp + (size_t)(wi * NW + tid) * DIM + h * DH);
#pragma unroll
    for (int i = 0; i < 16; i++) {
        op[i] = make_float4(acc[4 * i] * inv, acc[4 * i + 1] * inv,
                            acc[4 * i + 2] * inv, acc[4 * i + 3] * inv);
    }
}

// ---------------- launcher ----------------
extern "C" void kernel_launch(void* const* d_in, const int* in_sizes, int n_in,
                              void* d_out, int out_size) {
    const float* x      = (const float*)d_in[0];
    const float* rel    = (const float*)d_in[1];
    const float* ln1_g  = (const float*)d_in[2];
    const float* ln1_b  = (const float*)d_in[3];
    const float* qkv_w  = (const float*)d_in[4];
    const float* qkv_b  = (const float*)d_in[5];
    const float* proj_w = (const float*)d_in[6];
    const float* proj_b = (const float*)d_in[7];
    const float* ln2_g  = (const float*)d_in[8];
    const float* ln2_b  = (const float*)d_in[9];
    const float* fc1_w  = (const float*)d_in[10];
    const float* fc1_b  = (const float*)d_in[11];
    const float* fc2_w  = (const float*)d_in[12];
    const float* fc2_b  = (const float*)d_in[13];
    float* out = (float*)d_out;

    float *p_xw, *p_qkv, *p_attnout, *p_x1, *p_ln2, *p_mlp;
    cudaGetSymbolAddress((void**)&p_xw,      g_xw);
    cudaGetSymbolAddress((void**)&p_qkv,     g_qkv);
    cudaGetSymbolAddress((void**)&p_attnout, g_attnout);
    cudaGetSymbolAddress((void**)&p_x1,      g_x1);
    cudaGetSymbolAddress((void**)&p_ln2,     g_ln2);
    cudaGetSymbolAddress((void**)&p_mlp,     g_mlp);

    const int attn_smem = 2 * NW * DH * (int)sizeof(float);  // 100352 B
    cudaFuncSetAttribute(attn_kernel, cudaFuncAttributeMaxDynamicSharedMemorySize, attn_smem);

    // 1. LN1 + window partition (zeros in padded tokens)
    ln1_window_kernel<<<MWIN, 256>>>(x, ln1_g, ln1_b, p_xw);

    // 2. QKV: [39200, 2304] = xw @ qkv_w^T + b
    sgemm128<0><<<dim3((MWIN + 127) / 128, QKV_N / 128), 256>>>(
        p_xw, qkv_w, qkv_b, p_qkv, nullptr, MWIN, QKV_N, DIM);

    // 3. Windowed attention with relative position bias
    attn_kernel<<<NWINTOT * HEADS, 224, attn_smem>>>(p_qkv, rel, p_attnout);

    // 4. Projection + window revert + residual -> g_x1
    sgemm128<1><<<dim3((MWIN + 127) / 128, DIM / 128), 256>>>(
        p_attnout, proj_w, proj_b, p_x1, x, MWIN, DIM, DIM);

    // 5. LN2
    ln_kernel<<<MTOK, 256>>>(p_x1, ln2_g, ln2_b, p_ln2);

    // 6. fc1 + exact GELU
    sgemm128<2><<<dim3(MTOK / 128, MLP_H / 128), 256>>>(
        p_ln2, fc1_w, fc1_b, p_mlp, nullptr, MTOK, MLP_H, DIM);

    // 7. fc2 + residual -> d_out
    sgemm128<3><<<dim3(MTOK / 128, DIM / 128), 256>>>(
        p_mlp, fc2_w, fc2_b, out, p_x1, MTOK, DIM, MLP_H);
}

// round 10
// speedup vs baseline: 2.8264x; 1.4406x over previous
#include <cuda_runtime.h>
#include <cuda_bf16.h>
#include <math.h>
#include <stdint.h>

// ---------------- problem constants ----------------
#define DIM     768
#define HEADS   12
#define DH      64
#define WIN     14
#define NW      196          // WIN*WIN
#define BATCH   8
#define H0      64
#define W0      64
#define NTOK    4096         // H0*W0
#define NWIN_D  5            // windows per spatial dim (70/14)
#define NWIN_B  25           // windows per batch image
#define NWINTOT 200          // BATCH * NWIN_B
#define MWIN    (NWINTOT*NW) // 39200 windowed tokens
#define MTOK    (BATCH*NTOK) // 32768 real tokens
#define MLP_H   3072
#define QKV_N   (3*DIM)      // 2304
#define SCALE   0.125f
#define EPS     1e-5f

// ---------------- scratch (static device globals; no allocations) ----------------
__device__ float g_xw[(size_t)MWIN * DIM];
__device__ float g_qkv[(size_t)MWIN * QKV_N];
__device__ float g_attnout[(size_t)MWIN * DIM];
__device__ float g_x1[(size_t)MTOK * DIM];
__device__ float g_ln2[(size_t)MTOK * DIM];
__device__ float g_mlp[(size_t)MTOK * MLP_H];

// ---------------- block reduction ----------------
__device__ __forceinline__ float block_reduce_sum_256(float v) {
    __shared__ float red[8];
    int lane = threadIdx.x & 31, wid = threadIdx.x >> 5;
#pragma unroll
    for (int o = 16; o; o >>= 1) v += __shfl_xor_sync(0xffffffffu, v, o);
    __syncthreads();
    if (lane == 0) red[wid] = v;
    __syncthreads();
    float s = red[0];
#pragma unroll
    for (int i = 1; i < 8; i++) s += red[i];
    return s;
}

// ---------------- LN1 + window partition (pads -> zero rows) ----------------
__global__ void __launch_bounds__(256)
ln1_window_kernel(const float* __restrict__ x,
                  const float* __restrict__ g,
                  const float* __restrict__ b,
                  float* __restrict__ y) {
    int wt = blockIdx.x;
    int wi = wt / NW, t = wt - wi * NW;
    int bb = wi / NWIN_B;
    int wrem = wi - bb * NWIN_B;
    int wr = wrem / NWIN_D, wc = wrem - wr * NWIN_D;
    int row = wr * WIN + t / WIN;
    int col = wc * WIN + (t % WIN);
    int tid = threadIdx.x;
    float* yr = y + (size_t)wt * DIM;
    if (row >= H0 || col >= W0) {
        yr[tid] = 0.f; yr[tid + 256] = 0.f; yr[tid + 512] = 0.f;
        return;
    }
    const float* xr = x + ((size_t)bb * NTOK + row * W0 + col) * DIM;
    float v0 = xr[tid], v1 = xr[tid + 256], v2 = xr[tid + 512];
    float mean = block_reduce_sum_256(v0 + v1 + v2) * (1.0f / DIM);
    float d0 = v0 - mean, d1 = v1 - mean, d2 = v2 - mean;
    float var = block_reduce_sum_256(d0 * d0 + d1 * d1 + d2 * d2) * (1.0f / DIM);
    float rs = rsqrtf(var + EPS);
    yr[tid]       = d0 * rs * g[tid]       + b[tid];
    yr[tid + 256] = d1 * rs * g[tid + 256] + b[tid + 256];
    yr[tid + 512] = d2 * rs * g[tid + 512] + b[tid + 512];
}

// ---------------- plain LN (rows of 768) ----------------
__global__ void __launch_bounds__(256)
ln_kernel(const float* __restrict__ in,
          const float* __restrict__ g,
          const float* __restrict__ b,
          float* __restrict__ out) {
    size_t row = blockIdx.x;
    int tid = threadIdx.x;
    const float* xr = in + row * DIM;
    float v0 = xr[tid], v1 = xr[tid + 256], v2 = xr[tid + 512];
    float mean = block_reduce_sum_256(v0 + v1 + v2) * (1.0f / DIM);
    float d0 = v0 - mean, d1 = v1 - mean, d2 = v2 - mean;
    float var = block_reduce_sum_256(d0 * d0 + d1 * d1 + d2 * d2) * (1.0f / DIM);
    float rs = rsqrtf(var + EPS);
    float* yr = out + row * DIM;
    yr[tid]       = d0 * rs * g[tid]       + b[tid];
    yr[tid + 256] = d1 * rs * g[tid + 256] + b[tid + 256];
    yr[tid + 512] = d2 * rs * g[tid + 512] + b[tid + 512];
}

// ---------------- bf16 helpers ----------------
__device__ __forceinline__ void split_pack(float x0, float x1,
                                           uint32_t& hi, uint32_t& lo) {
    __nv_bfloat16 h0 = __float2bfloat16_rn(x0);
    __nv_bfloat16 h1 = __float2bfloat16_rn(x1);
    float r0 = x0 - __bfloat162float(h0);
    float r1 = x1 - __bfloat162float(h1);
    __nv_bfloat16 l0 = __float2bfloat16_rn(r0);
    __nv_bfloat16 l1 = __float2bfloat16_rn(r1);
    hi = ((uint32_t)__bfloat16_as_ushort(h1) << 16) | __bfloat16_as_ushort(h0);
    lo = ((uint32_t)__bfloat16_as_ushort(l1) << 16) | __bfloat16_as_ushort(l0);
}

// m16n8k16 bf16 mma: a = 4x u32 (bf16x2), b = 2x u32, c/d = 4x f32.
__device__ __forceinline__ void mma_bf16(float* c, const uint32_t* a,
                                         uint32_t b0, uint32_t b1) {
    asm volatile(
        "mma.sync.aligned.m16n8k16.row.col.f32.bf16.bf16.f32 "
        "{%0,%1,%2,%3}, {%4,%5,%6,%7}, {%8,%9}, {%0,%1,%2,%3};"
        : "+f"(c[0]), "+f"(c[1]), "+f"(c[2]), "+f"(c[3])
        : "r"(a[0]), "r"(a[1]), "r"(a[2]), "r"(a[3]), "r"(b0), "r"(b1));
}

// ---------------- 128x128x16 split-bf16 tensor-core GEMM (NT) ----------------
// C[M,N] = A[M,K] * W[N,K]^T + bias, fp32-accurate via hi/lo bf16 split:
//   A*B ~= Ah*Bh + Ah*Bl + Al*Bh   (Al*Bl ~ 2^-18 relative, dropped)
// 256 threads = 8 warps (4 x 2); warp tile 32x64 = 2 (m16) x 8 (n8) mma tiles.
//  EPI 0: store C
//  EPI 1: window-revert scatter: C[pos] = extra[pos] + val (pad tokens dropped)
//  EPI 2: store exact GELU(val)
//  EPI 3: store val + extra[m*N+n]
#define PITCH 9
template <int EPI>
__global__ void __launch_bounds__(256, 1)
bgemm128(const float* __restrict__ A, const float* __restrict__ W,
         const float* __restrict__ bias, float* __restrict__ C,
         const float* __restrict__ extra, int M, int N, int K) {
    __shared__ uint32_t sAh[2][128][PITCH];
    __shared__ uint32_t sAl[2][128][PITCH];
    __shared__ uint32_t sBh[2][128][PITCH];
    __shared__ uint32_t sBl[2][128][PITCH];
    const int tid  = threadIdx.x;
    const int row0 = blockIdx.x * 128, col0 = blockIdx.y * 128;

    const int wid  = tid >> 5, lane = tid & 31;
    const int wm   = wid & 3, wn = wid >> 2;   // warp tile: rows wm*32, cols wn*64
    const int g    = lane >> 2, t4 = lane & 3; // fragment coords

    // gmem load mapping: thread -> row = tid>>1, k-offset = (tid&1)*8
    const int lr = tid >> 1;
    const int lk = (tid & 1) * 8;
    const int p0 = lk >> 1;                    // pair index base: 0 or 4
    const bool aval = (row0 + lr) < M;
    const float* Ap = A + (size_t)(row0 + lr) * K + lk;
    const float* Bp = W + (size_t)(col0 + lr) * K + lk;

    float acc[2][8][4];
#pragma unroll
    for (int i = 0; i < 2; i++)
#pragma unroll
        for (int j = 0; j < 8; j++)
#pragma unroll
            for (int p = 0; p < 4; p++) acc[i][j][p] = 0.f;

    const int nt = K >> 4;
    float4 ra0, ra1, rb0, rb1;
    ra0 = aval ? *(const float4*)Ap       : make_float4(0,0,0,0);
    ra1 = aval ? *(const float4*)(Ap + 4) : make_float4(0,0,0,0);
    rb0 = *(const float4*)Bp;
    rb1 = *(const float4*)(Bp + 4);
    {
        split_pack(ra0.x, ra0.y, sAh[0][lr][p0+0], sAl[0][lr][p0+0]);
        split_pack(ra0.z, ra0.w, sAh[0][lr][p0+1], sAl[0][lr][p0+1]);
        split_pack(ra1.x, ra1.y, sAh[0][lr][p0+2], sAl[0][lr][p0+2]);
        split_pack(ra1.z, ra1.w, sAh[0][lr][p0+3], sAl[0][lr][p0+3]);
        split_pack(rb0.x, rb0.y, sBh[0][lr][p0+0], sBl[0][lr][p0+0]);
        split_pack(rb0.z, rb0.w, sBh[0][lr][p0+1], sBl[0][lr][p0+1]);
        split_pack(rb1.x, rb1.y, sBh[0][lr][p0+2], sBl[0][lr][p0+2]);
        split_pack(rb1.z, rb1.w, sBh[0][lr][p0+3], sBl[0][lr][p0+3]);
    }
    __syncthreads();

    for (int kt = 0; kt < nt; kt++) {
        const int cur = kt & 1;
        if (kt + 1 < nt) {
            const float* ap = Ap + (size_t)(kt + 1) * 16;
            const float* bp = Bp + (size_t)(kt + 1) * 16;
            ra0 = aval ? *(const float4*)ap       : make_float4(0,0,0,0);
            ra1 = aval ? *(const float4*)(ap + 4) : make_float4(0,0,0,0);
            rb0 = *(const float4*)bp;
            rb1 = *(const float4*)(bp + 4);
        }
        // A fragments for both m16 tiles (hi and lo)
        uint32_t ah[2][4], al[2][4];
#pragma unroll
        for (int i = 0; i < 2; i++) {
            const int base = wm * 32 + i * 16;
            ah[i][0] = sAh[cur][base + g    ][t4];
            ah[i][1] = sAh[cur][base + 8 + g][t4];
            ah[i][2] = sAh[cur][base + g    ][t4 + 4];
            ah[i][3] = sAh[cur][base + 8 + g][t4 + 4];
            al[i][0] = sAl[cur][base + g    ][t4];
            al[i][1] = sAl[cur][base + 8 + g][t4];
            al[i][2] = sAl[cur][base + g    ][t4 + 4];
            al[i][3] = sAl[cur][base + 8 + g][t4 + 4];
        }
#pragma unroll
        for (int j = 0; j < 8; j++) {
            const int nrow = wn * 64 + j * 8 + g;
            uint32_t bh0 = sBh[cur][nrow][t4], bh1 = sBh[cur][nrow][t4 + 4];
            uint32_t bl0 = sBl[cur][nrow][t4], bl1 = sBl[cur][nrow][t4 + 4];
#pragma unroll
            for (int i = 0; i < 2; i++) {
                mma_bf16(acc[i][j], ah[i], bh0, bh1);   // Ah*Bh
                mma_bf16(acc[i][j], ah[i], bl0, bl1);   // Ah*Bl
                mma_bf16(acc[i][j], al[i], bh0, bh1);   // Al*Bh
            }
        }
        if (kt + 1 < nt) {
            const int nxt = cur ^ 1;
            split_pack(ra0.x, ra0.y, sAh[nxt][lr][p0+0], sAl[nxt][lr][p0+0]);
            split_pack(ra0.z, ra0.w, sAh[nxt][lr][p0+1], sAl[nxt][lr][p0+1]);
            split_pack(ra1.x, ra1.y, sAh[nxt][lr][p0+2], sAl[nxt][lr][p0+2]);
            split_pack(ra1.z, ra1.w, sAh[nxt][lr][p0+3], sAl[nxt][lr][p0+3]);
            split_pack(rb0.x, rb0.y, sBh[nxt][lr][p0+0], sBl[nxt][lr][p0+0]);
            split_pack(rb0.z, rb0.w, sBh[nxt][lr][p0+1], sBl[nxt][lr][p0+1]);
            split_pack(rb1.x, rb1.y, sBh[nxt][lr][p0+2], sBl[nxt][lr][p0+2]);
            split_pack(rb1.z, rb1.w, sBh[nxt][lr][p0+3], sBl[nxt][lr][p0+3]);
            __syncthreads();
        }
    }

    // ---------------- epilogue ----------------
    // thread owns rows {wm*32 + i*16 + r*8 + g}, cols col0 + {wn*64 + j*8 + 2*t4 + p}
    float bcol[8][2];
#pragma unroll
    for (int j = 0; j < 8; j++) {
        int c = col0 + wn * 64 + j * 8 + 2 * t4;
        bcol[j][0] = bias[c];
        bcol[j][1] = bias[c + 1];
    }
#pragma unroll
    for (int i = 0; i < 2; i++) {
#pragma unroll
        for (int r = 0; r < 2; r++) {
            int m = row0 + wm * 32 + i * 16 + r * 8 + g;
            if (m >= M) continue;
            if (EPI == 1) {
                int wi = m / NW, t = m - wi * NW;
                int bb = wi / NWIN_B;
                int wrem = wi - bb * NWIN_B;
                int wr = wrem / NWIN_D, wc = wrem - wr * NWIN_D;
                int rr = wr * WIN + t / WIN;
                int cc = wc * WIN + (t % WIN);
                if (rr < H0 && cc < W0) {
                    size_t ob = ((size_t)bb * NTOK + rr * W0 + cc) * DIM;
#pragma unroll
                    for (int j = 0; j < 8; j++) {
                        // FIX (R9): col0 was missing here in R4-R8 — all column
                        // blocks scattered into cols 0..127, corrupting g_x1.
                        size_t o = ob + col0 + wn * 64 + j * 8 + 2 * t4;
                        float v0 = acc[i][j][r * 2]     + bcol[j][0] + extra[o];
                        float v1 = acc[i][j][r * 2 + 1] + bcol[j][1] + extra[o + 1];
                        *(float2*)&C[o] = make_float2(v0, v1);
                    }
                }
            } else {
                size_t ob = (size_t)m * N + col0 + wn * 64;
#pragma unroll
                for (int j = 0; j < 8; j++) {
                    size_t o = ob + j * 8 + 2 * t4;
                    float v0 = acc[i][j][r * 2]     + bcol[j][0];
                    float v1 = acc[i][j][r * 2 + 1] + bcol[j][1];
                    if (EPI == 2) {
                        v0 = 0.5f * v0 * (1.0f + erff(v0 * 0.70710678118654752f));
                        v1 = 0.5f * v1 * (1.0f + erff(v1 * 0.70710678118654752f));
                    } else if (EPI == 3) {
                        v0 += extra[o];
                        v1 += extra[o + 1];
                    }
                    *(float2*)&C[o] = make_float2(v0, v1);
                }
            }
        }
    }
}

// ---------------- windowed attention, one (window, head) per block ----------------
__global__ void __launch_bounds__(224)
attn_kernel(const float* __restrict__ qkv,
            const float* __restrict__ rel,
            float* __restrict__ outp) {
    extern __shared__ float sm[];
    float* sk = sm;
    float* sv = sm + NW * DH;
    int wi = blockIdx.x / HEADS;
    int h  = blockIdx.x - wi * HEADS;
    int tid = threadIdx.x;
    size_t base = (size_t)wi * NW * QKV_N + h * DH;
    for (int idx = tid; idx < NW * DH; idx += 224) {
        int t = idx >> 6, d = idx & 63;
        size_t o = base + (size_t)t * QKV_N + d;
        sk[idx] = qkv[o + DIM];
        sv[idx] = qkv[o + 2 * DIM];
    }
    __syncthreads();
    if (tid >= NW) return;

    float q[DH];
    {
        const float4* qp = (const float4*)(qkv + base + (size_t)tid * QKV_N);
#pragma unroll
        for (int i = 0; i < 16; i++) {
            float4 qq = qp[i];
            q[4 * i]     = qq.x * SCALE;
            q[4 * i + 1] = qq.y * SCALE;
            q[4 * i + 2] = qq.z * SCALE;
            q[4 * i + 3] = qq.w * SCALE;
        }
    }
    float acc[DH];
#pragma unroll
    for (int i = 0; i < DH; i++) acc[i] = 0.f;
    float mx = -1e30f, l = 0.f;
    const float* brow = rel + ((size_t)h * NW + tid) * NW;

    for (int j = 0; j < NW; j++) {
        const float4* kp = (const float4*)(sk + j * DH);
        float s = 0.f;
#pragma unroll
        for (int i = 0; i < 16; i++) {
            float4 kk = kp[i];
            s += q[4 * i] * kk.x + q[4 * i + 1] * kk.y
               + q[4 * i + 2] * kk.z + q[4 * i + 3] * kk.w;
        }
        s += brow[j];
        const float4* vp = (const float4*)(sv + j * DH);
        if (s <= mx) {
            float p = __expf(s - mx);
            l += p;
#pragma unroll
            for (int i = 0; i < 16; i++) {
                float4 vv = vp[i];
                acc[4 * i]     += p * vv.x;
                acc[4 * i + 1] += p * vv.y;
                acc[4 * i + 2] += p * vv.z;
                acc[4 * i + 3] += p * vv.w;
            }
        } else {
            float c = __expf(mx - s);
            l = l * c + 1.f;
            mx = s;
#pragma unroll
            for (int i = 0; i < 16; i++) {
                float4 vv = vp[i];
                acc[4 * i]     = acc[4 * i]     * c + vv.x;
                acc[4 * i + 1] = acc[4 * i + 1] * c + vv.y;
                acc[4 * i + 2] = acc[4 * i + 2] * c + vv.z;
                acc[4 * i + 3] = acc[4 * i + 3] * c + vv.w;
            }
        }
    }
    float inv = 1.0f / l;
    float4* op = (float4*)(outp + (size_t)(wi * NW + tid) * DIM + h * DH);
#pragma unroll
    for (int i = 0; i < 16; i++) {
        op[i] = make_float4(acc[4 * i] * inv, acc[4 * i + 1] * inv,
                            acc[4 * i + 2] * inv, acc[4 * i + 3] * inv);
    }
}

// ---------------- launcher ----------------
extern "C" void kernel_launch(void* const* d_in, const int* in_sizes, int n_in,
                              void* d_out, int out_size) {
    const float* x      = (const float*)d_in[0];
    const float* rel    = (const float*)d_in[1];
    const float* ln1_g  = (const float*)d_in[2];
    const float* ln1_b  = (const float*)d_in[3];
    const float* qkv_w  = (const float*)d_in[4];
    const float* qkv_b  = (const float*)d_in[5];
    const float* proj_w = (const float*)d_in[6];
    const float* proj_b = (const float*)d_in[7];
    const float* ln2_g  = (const float*)d_in[8];
    const float* ln2_b  = (const float*)d_in[9];
    const float* fc1_w  = (const float*)d_in[10];
    const float* fc1_b  = (const float*)d_in[11];
    const float* fc2_w  = (const float*)d_in[12];
    const float* fc2_b  = (const float*)d_in[13];
    float* out = (float*)d_out;

    float *p_xw, *p_qkv, *p_attnout, *p_x1, *p_ln2, *p_mlp;
    cudaGetSymbolAddress((void**)&p_xw,      g_xw);
    cudaGetSymbolAddress((void**)&p_qkv,     g_qkv);
    cudaGetSymbolAddress((void**)&p_attnout, g_attnout);
    cudaGetSymbolAddress((void**)&p_x1,      g_x1);
    cudaGetSymbolAddress((void**)&p_ln2,     g_ln2);
    cudaGetSymbolAddress((void**)&p_mlp,     g_mlp);

    const int attn_smem = 2 * NW * DH * (int)sizeof(float);  // 100352 B
    cudaFuncSetAttribute(attn_kernel, cudaFuncAttributeMaxDynamicSharedMemorySize, attn_smem);

    // 1. LN1 + window partition
    ln1_window_kernel<<<MWIN, 256>>>(x, ln1_g, ln1_b, p_xw);

    // 2. QKV
    bgemm128<0><<<dim3((MWIN + 127) / 128, QKV_N / 128), 256>>>(
        p_xw, qkv_w, qkv_b, p_qkv, nullptr, MWIN, QKV_N, DIM);

    // 3. Windowed attention
    attn_kernel<<<NWINTOT * HEADS, 224, attn_smem>>>(p_qkv, rel, p_attnout);

    // 4. Projection + window revert + residual
    bgemm128<1><<<dim3((MWIN + 127) / 128, DIM / 128), 256>>>(
        p_attnout, proj_w, proj_b, p_x1, x, MWIN, DIM, DIM);

    // 5. LN2
    ln_kernel<<<MTOK, 256>>>(p_x1, ln2_g, ln2_b, p_ln2);

    // 6. fc1 + exact GELU
    bgemm128<2><<<dim3(MTOK / 128, MLP_H / 128), 256>>>(
        p_ln2, fc1_w, fc1_b, p_mlp, nullptr, MTOK, MLP_H, DIM);

    // 7. fc2 + residual -> d_out
    bgemm128<3><<<dim3(MTOK / 128, DIM / 128), 256>>>(
        p_mlp, fc2_w, fc2_b, out, p_x1, MTOK, DIM, MLP_H);
}

// round 11
// speedup vs baseline: 4.1398x; 1.4647x over previous
#include <cuda_runtime.h>
#include <math.h>
#include <stdint.h>

// ---------------- problem constants ----------------
#define DIM     768
#define HEADS   12
#define DH      64
#define WIN     14
#define NW      196          // WIN*WIN
#define BATCH   8
#define H0      64
#define W0      64
#define NTOK    4096         // H0*W0
#define NWIN_D  5            // windows per spatial dim (70/14)
#define NWIN_B  25           // windows per batch image
#define NWINTOT 200          // BATCH * NWIN_B
#define MWIN    (NWINTOT*NW) // 39200 windowed tokens
#define MTOK    (BATCH*NTOK) // 32768 real tokens
#define MLP_H   3072
#define QKV_N   (3*DIM)      // 2304
#define SCALE   0.125f
#define EPS     1e-5f

// ---------------- scratch (static device globals; no allocations) ----------------
__device__ float g_xw[(size_t)MWIN * DIM];
__device__ float g_qkv[(size_t)MWIN * QKV_N];
__device__ float g_attnout[(size_t)MWIN * DIM];
__device__ float g_x1[(size_t)MTOK * DIM];
__device__ float g_ln2[(size_t)MTOK * DIM];
__device__ float g_mlp[(size_t)MTOK * MLP_H];

// ---------------- block reduction ----------------
__device__ __forceinline__ float block_reduce_sum_256(float v) {
    __shared__ float red[8];
    int lane = threadIdx.x & 31, wid = threadIdx.x >> 5;
#pragma unroll
    for (int o = 16; o; o >>= 1) v += __shfl_xor_sync(0xffffffffu, v, o);
    __syncthreads();
    if (lane == 0) red[wid] = v;
    __syncthreads();
    float s = red[0];
#pragma unroll
    for (int i = 1; i < 8; i++) s += red[i];
    return s;
}

// ---------------- LN1 + window partition (pads -> zero rows) ----------------
__global__ void __launch_bounds__(256)
ln1_window_kernel(const float* __restrict__ x,
                  const float* __restrict__ g,
                  const float* __restrict__ b,
                  float* __restrict__ y) {
    int wt = blockIdx.x;
    int wi = wt / NW, t = wt - wi * NW;
    int bb = wi / NWIN_B;
    int wrem = wi - bb * NWIN_B;
    int wr = wrem / NWIN_D, wc = wrem - wr * NWIN_D;
    int row = wr * WIN + t / WIN;
    int col = wc * WIN + (t % WIN);
    int tid = threadIdx.x;
    float* yr = y + (size_t)wt * DIM;
    if (row >= H0 || col >= W0) {
        yr[tid] = 0.f; yr[tid + 256] = 0.f; yr[tid + 512] = 0.f;
        return;
    }
    const float* xr = x + ((size_t)bb * NTOK + row * W0 + col) * DIM;
    float v0 = xr[tid], v1 = xr[tid + 256], v2 = xr[tid + 512];
    float mean = block_reduce_sum_256(v0 + v1 + v2) * (1.0f / DIM);
    float d0 = v0 - mean, d1 = v1 - mean, d2 = v2 - mean;
    float var = block_reduce_sum_256(d0 * d0 + d1 * d1 + d2 * d2) * (1.0f / DIM);
    float rs = rsqrtf(var + EPS);
    yr[tid]       = d0 * rs * g[tid]       + b[tid];
    yr[tid + 256] = d1 * rs * g[tid + 256] + b[tid + 256];
    yr[tid + 512] = d2 * rs * g[tid + 512] + b[tid + 512];
}

// ---------------- plain LN (rows of 768) ----------------
__global__ void __launch_bounds__(256)
ln_kernel(const float* __restrict__ in,
          const float* __restrict__ g,
          const float* __restrict__ b,
          float* __restrict__ out) {
    size_t row = blockIdx.x;
    int tid = threadIdx.x;
    const float* xr = in + row * DIM;
    float v0 = xr[tid], v1 = xr[tid + 256], v2 = xr[tid + 512];
    float mean = block_reduce_sum_256(v0 + v1 + v2) * (1.0f / DIM);
    float d0 = v0 - mean, d1 = v1 - mean, d2 = v2 - mean;
    float var = block_reduce_sum_256(d0 * d0 + d1 * d1 + d2 * d2) * (1.0f / DIM);
    float rs = rsqrtf(var + EPS);
    float* yr = out + row * DIM;
    yr[tid]       = d0 * rs * g[tid]       + b[tid];
    yr[tid + 256] = d1 * rs * g[tid + 256] + b[tid + 256];
    yr[tid + 512] = d2 * rs * g[tid + 512] + b[tid + 512];
}

// ---------------- tf32 helpers ----------------
__device__ __forceinline__ float to_tf32(float x) {
    float r;
    asm("cvt.rna.tf32.f32 %0, %1;" : "=f"(r) : "f"(x));
    return r;
}
__device__ __forceinline__ void mma_tf32(float* c, const float* a, const float* b) {
    uint32_t a0 = __float_as_uint(a[0]), a1 = __float_as_uint(a[1]);
    uint32_t a2 = __float_as_uint(a[2]), a3 = __float_as_uint(a[3]);
    uint32_t b0 = __float_as_uint(b[0]), b1 = __float_as_uint(b[1]);
    asm volatile(
        "mma.sync.aligned.m16n8k8.row.col.f32.tf32.tf32.f32 "
        "{%0,%1,%2,%3}, {%4,%5,%6,%7}, {%8,%9}, {%0,%1,%2,%3};"
        : "+f"(c[0]), "+f"(c[1]), "+f"(c[2]), "+f"(c[3])
        : "r"(a0), "r"(a1), "r"(a2), "r"(a3), "r"(b0), "r"(b1));
}

// ---------------- 128x128x16 tf32 tensor-core GEMM (NT) ----------------
// C[M,N] = A[M,K] * W[N,K]^T + bias. 256 threads = 8 warps (4 x 2).
// Each warp: 32x64 output via 2 (m16) x 8 (n8) mma tiles.
// tf32 m16n8k8 fragment layout — VALIDATED (R4 output matched the certified
// bf16 path bit-for-bit through the block):
//   A: a0=(g,t4) a1=(g+8,t4) a2=(g,t4+4) a3=(g+8,t4+4)
//   B: b0=(k=t4,n=g) b1=(k=t4+4,n=g)
//   C: c0=(g,2t4) c1=(g,2t4+1) c2=(g+8,2t4) c3=(g+8,2t4+1)
//  EPI 0: store C
//  EPI 1: window-revert scatter: C[pos] = extra[pos] + val (pad tokens dropped)
//  EPI 2: store exact GELU(val)
//  EPI 3: store val + extra[m*N+n]
#define SPITCH 20
template <int EPI>
__global__ void __launch_bounds__(256, 2)
tgemm128(const float* __restrict__ A, const float* __restrict__ W,
         const float* __restrict__ bias, float* __restrict__ C,
         const float* __restrict__ extra, int M, int N, int K) {
    __shared__ float sA[2][128][SPITCH];
    __shared__ float sB[2][128][SPITCH];
    const int tid  = threadIdx.x;
    const int row0 = blockIdx.x * 128, col0 = blockIdx.y * 128;

    const int wid  = tid >> 5, lane = tid & 31;
    const int wm   = wid & 3, wn = wid >> 2;   // warp tile: rows wm*32, cols wn*64
    const int g    = lane >> 2, t4 = lane & 3; // fragment coords

    // gmem load mapping: thread -> row = tid>>1, k-offset = (tid&1)*8
    const int lr = tid >> 1;
    const int lk = (tid & 1) * 8;
    const bool aval = (row0 + lr) < M;
    const float* Ap = A + (size_t)(row0 + lr) * K + lk;
    const float* Bp = W + (size_t)(col0 + lr) * K + lk;

    float acc[2][8][4];
#pragma unroll
    for (int i = 0; i < 2; i++)
#pragma unroll
        for (int j = 0; j < 8; j++)
#pragma unroll
            for (int p = 0; p < 4; p++) acc[i][j][p] = 0.f;

    const int nt = K >> 4;
    float4 ra0, ra1, rb0, rb1;
    ra0 = aval ? *(const float4*)Ap       : make_float4(0,0,0,0);
    ra1 = aval ? *(const float4*)(Ap + 4) : make_float4(0,0,0,0);
    rb0 = *(const float4*)Bp;
    rb1 = *(const float4*)(Bp + 4);
    {
        float* da = &sA[0][lr][lk];
        float* db = &sB[0][lr][lk];
        da[0]=to_tf32(ra0.x); da[1]=to_tf32(ra0.y); da[2]=to_tf32(ra0.z); da[3]=to_tf32(ra0.w);
        da[4]=to_tf32(ra1.x); da[5]=to_tf32(ra1.y); da[6]=to_tf32(ra1.z); da[7]=to_tf32(ra1.w);
        db[0]=to_tf32(rb0.x); db[1]=to_tf32(rb0.y); db[2]=to_tf32(rb0.z); db[3]=to_tf32(rb0.w);
        db[4]=to_tf32(rb1.x); db[5]=to_tf32(rb1.y); db[6]=to_tf32(rb1.z); db[7]=to_tf32(rb1.w);
    }
    __syncthreads();

    for (int kt = 0; kt < nt; kt++) {
        const int cur = kt & 1;
        if (kt + 1 < nt) {
            const float* ap = Ap + (size_t)(kt + 1) * 16;
            const float* bp = Bp + (size_t)(kt + 1) * 16;
            ra0 = aval ? *(const float4*)ap       : make_float4(0,0,0,0);
            ra1 = aval ? *(const float4*)(ap + 4) : make_float4(0,0,0,0);
            rb0 = *(const float4*)bp;
            rb1 = *(const float4*)(bp + 4);
        }
#pragma unroll
        for (int ks = 0; ks < 2; ks++) {
            const int k0 = ks * 8;
            float af[2][4], bf[8][2];
#pragma unroll
            for (int i = 0; i < 2; i++) {
                const int mrow = wm * 32 + i * 16 + g;
                af[i][0] = sA[cur][mrow    ][k0 + t4];
                af[i][1] = sA[cur][mrow + 8][k0 + t4];
                af[i][2] = sA[cur][mrow    ][k0 + t4 + 4];
                af[i][3] = sA[cur][mrow + 8][k0 + t4 + 4];
            }
#pragma unroll
            for (int j = 0; j < 8; j++) {
                const int nrow = wn * 64 + j * 8 + g;
                bf[j][0] = sB[cur][nrow][k0 + t4];
                bf[j][1] = sB[cur][nrow][k0 + t4 + 4];
            }
#pragma unroll
            for (int i = 0; i < 2; i++)
#pragma unroll
                for (int j = 0; j < 8; j++)
                    mma_tf32(acc[i][j], af[i], bf[j]);
        }
        if (kt + 1 < nt) {
            const int nxt = cur ^ 1;
            float* da = &sA[nxt][lr][lk];
            float* db = &sB[nxt][lr][lk];
            da[0]=to_tf32(ra0.x); da[1]=to_tf32(ra0.y); da[2]=to_tf32(ra0.z); da[3]=to_tf32(ra0.w);
            da[4]=to_tf32(ra1.x); da[5]=to_tf32(ra1.y); da[6]=to_tf32(ra1.z); da[7]=to_tf32(ra1.w);
            db[0]=to_tf32(rb0.x); db[1]=to_tf32(rb0.y); db[2]=to_tf32(rb0.z); db[3]=to_tf32(rb0.w);
            db[4]=to_tf32(rb1.x); db[5]=to_tf32(rb1.y); db[6]=to_tf32(rb1.z); db[7]=to_tf32(rb1.w);
            __syncthreads();
        }
    }

    // ---------------- epilogue ----------------
    // thread owns rows {wm*32 + i*16 + r*8 + g}, cols col0 + {wn*64 + j*8 + 2*t4 + p}
    float bcol[8][2];
#pragma unroll
    for (int j = 0; j < 8; j++) {
        int c = col0 + wn * 64 + j * 8 + 2 * t4;
        bcol[j][0] = bias[c];
        bcol[j][1] = bias[c + 1];
    }
#pragma unroll
    for (int i = 0; i < 2; i++) {
#pragma unroll
        for (int r = 0; r < 2; r++) {
            int m = row0 + wm * 32 + i * 16 + r * 8 + g;
            if (m >= M) continue;
            if (EPI == 1) {
                int wi = m / NW, t = m - wi * NW;
                int bb = wi / NWIN_B;
                int wrem = wi - bb * NWIN_B;
                int wr = wrem / NWIN_D, wc = wrem - wr * NWIN_D;
                int rr = wr * WIN + t / WIN;
                int cc = wc * WIN + (t % WIN);
                if (rr < H0 && cc < W0) {
                    size_t ob = ((size_t)bb * NTOK + rr * W0 + cc) * DIM;
#pragma unroll
                    for (int j = 0; j < 8; j++) {
                        // col0 included (R9 fix)
                        size_t o = ob + col0 + wn * 64 + j * 8 + 2 * t4;
                        float v0 = acc[i][j][r * 2]     + bcol[j][0] + extra[o];
                        float v1 = acc[i][j][r * 2 + 1] + bcol[j][1] + extra[o + 1];
                        *(float2*)&C[o] = make_float2(v0, v1);
                    }
                }
            } else {
                size_t ob = (size_t)m * N + col0 + wn * 64;
#pragma unroll
                for (int j = 0; j < 8; j++) {
                    size_t o = ob + j * 8 + 2 * t4;
                    float v0 = acc[i][j][r * 2]     + bcol[j][0];
                    float v1 = acc[i][j][r * 2 + 1] + bcol[j][1];
                    if (EPI == 2) {
                        v0 = 0.5f * v0 * (1.0f + erff(v0 * 0.70710678118654752f));
                        v1 = 0.5f * v1 * (1.0f + erff(v1 * 0.70710678118654752f));
                    } else if (EPI == 3) {
                        v0 += extra[o];
                        v1 += extra[o + 1];
                    }
                    *(float2*)&C[o] = make_float2(v0, v1);
                }
            }
        }
    }
}

// ---------------- windowed attention, one (window, head) per block ----------------
__global__ void __launch_bounds__(224)
attn_kernel(const float* __restrict__ qkv,
            const float* __restrict__ rel,
            float* __restrict__ outp) {
    extern __shared__ float sm[];
    float* sk = sm;
    float* sv = sm + NW * DH;
    int wi = blockIdx.x / HEADS;
    int h  = blockIdx.x - wi * HEADS;
    int tid = threadIdx.x;
    size_t base = (size_t)wi * NW * QKV_N + h * DH;
    for (int idx = tid; idx < NW * DH; idx += 224) {
        int t = idx >> 6, d = idx & 63;
        size_t o = base + (size_t)t * QKV_N + d;
        sk[idx] = qkv[o + DIM];
        sv[idx] = qkv[o + 2 * DIM];
    }
    __syncthreads();
    if (tid >= NW) return;

    float q[DH];
    {
        const float4* qp = (const float4*)(qkv + base + (size_t)tid * QKV_N);
#pragma unroll
        for (int i = 0; i < 16; i++) {
            float4 qq = qp[i];
            q[4 * i]     = qq.x * SCALE;
            q[4 * i + 1] = qq.y * SCALE;
            q[4 * i + 2] = qq.z * SCALE;
            q[4 * i + 3] = qq.w * SCALE;
        }
    }
    float acc[DH];
#pragma unroll
    for (int i = 0; i < DH; i++) acc[i] = 0.f;
    float mx = -1e30f, l = 0.f;
    const float* brow = rel + ((size_t)h * NW + tid) * NW;

    for (int j = 0; j < NW; j++) {
        const float4* kp = (const float4*)(sk + j * DH);
        float s = 0.f;
#pragma unroll
        for (int i = 0; i < 16; i++) {
            float4 kk = kp[i];
            s += q[4 * i] * kk.x + q[4 * i + 1] * kk.y
               + q[4 * i + 2] * kk.z + q[4 * i + 3] * kk.w;
        }
        s += brow[j];
        const float4* vp = (const float4*)(sv + j * DH);
        if (s <= mx) {
            float p = __expf(s - mx);
            l += p;
#pragma unroll
            for (int i = 0; i < 16; i++) {
                float4 vv = vp[i];
                acc[4 * i]     += p * vv.x;
                acc[4 * i + 1] += p * vv.y;
                acc[4 * i + 2] += p * vv.z;
                acc[4 * i + 3] += p * vv.w;
            }
        } else {
            float c = __expf(mx - s);
            l = l * c + 1.f;
            mx = s;
#pragma unroll
            for (int i = 0; i < 16; i++) {
                float4 vv = vp[i];
                acc[4 * i]     = acc[4 * i]     * c + vv.x;
                acc[4 * i + 1] = acc[4 * i + 1] * c + vv.y;
                acc[4 * i + 2] = acc[4 * i + 2] * c + vv.z;
                acc[4 * i + 3] = acc[4 * i + 3] * c + vv.w;
            }
        }
    }
    float inv = 1.0f / l;
    float4* op = (float4*)(outp + (size_t)(wi * NW + tid) * DIM + h * DH);
#pragma unroll
    for (int i = 0; i < 16; i++) {
        op[i] = make_float4(acc[4 * i] * inv, acc[4 * i + 1] * inv,
                            acc[4 * i + 2] * inv, acc[4 * i + 3] * inv);
    }
}

// ---------------- launcher ----------------
extern "C" void kernel_launch(void* const* d_in, const int* in_sizes, int n_in,
                              void* d_out, int out_size) {
    const float* x      = (const float*)d_in[0];
    const float* rel    = (const float*)d_in[1];
    const float* ln1_g  = (const float*)d_in[2];
    const float* ln1_b  = (const float*)d_in[3];
    const float* qkv_w  = (const float*)d_in[4];
    const float* qkv_b  = (const float*)d_in[5];
    const float* proj_w = (const float*)d_in[6];
    const float* proj_b = (const float*)d_in[7];
    const float* ln2_g  = (const float*)d_in[8];
    const float* ln2_b  = (const float*)d_in[9];
    const float* fc1_w  = (const float*)d_in[10];
    const float* fc1_b  = (const float*)d_in[11];
    const float* fc2_w  = (const float*)d_in[12];
    const float* fc2_b  = (const float*)d_in[13];
    float* out = (float*)d_out;

    float *p_xw, *p_qkv, *p_attnout, *p_x1, *p_ln2, *p_mlp;
    cudaGetSymbolAddress((void**)&p_xw,      g_xw);
    cudaGetSymbolAddress((void**)&p_qkv,     g_qkv);
    cudaGetSymbolAddress((void**)&p_attnout, g_attnout);
    cudaGetSymbolAddress((void**)&p_x1,      g_x1);
    cudaGetSymbolAddress((void**)&p_ln2,     g_ln2);
    cudaGetSymbolAddress((void**)&p_mlp,     g_mlp);

    const int attn_smem = 2 * NW * DH * (int)sizeof(float);  // 100352 B
    cudaFuncSetAttribute(attn_kernel, cudaFuncAttributeMaxDynamicSharedMemorySize, attn_smem);

    // 1. LN1 + window partition
    ln1_window_kernel<<<MWIN, 256>>>(x, ln1_g, ln1_b, p_xw);

    // 2. QKV
    tgemm128<0><<<dim3((MWIN + 127) / 128, QKV_N / 128), 256>>>(
        p_xw, qkv_w, qkv_b, p_qkv, nullptr, MWIN, QKV_N, DIM);

    // 3. Windowed attention
    attn_kernel<<<NWINTOT * HEADS, 224, attn_smem>>>(p_qkv, rel, p_attnout);

    // 4. Projection + window revert + residual
    tgemm128<1><<<dim3((MWIN + 127) / 128, DIM / 128), 256>>>(
        p_attnout, proj_w, proj_b, p_x1, x, MWIN, DIM, DIM);

    // 5. LN2
    ln_kernel<<<MTOK, 256>>>(p_x1, ln2_g, ln2_b, p_ln2);

    // 6. fc1 + exact GELU
    tgemm128<2><<<dim3(MTOK / 128, MLP_H / 128), 256>>>(
        p_ln2, fc1_w, fc1_b, p_mlp, nullptr, MTOK, MLP_H, DIM);

    // 7. fc2 + residual -> d_out
    tgemm128<3><<<dim3(MTOK / 128, DIM / 128), 256>>>(
        p_mlp, fc2_w, fc2_b, out, p_x1, MTOK, DIM, MLP_H);
}